// round 12
// baseline (speedup 1.0000x reference)
#include <cuda_runtime.h>
#include <cuda_bf16.h>
#include <cuda_fp8.h>
#include <math.h>
#include <stdint.h>

// Fixed problem envelope (dataset: N=8192, d=1024). Requires N%128==0, d%64==0.
#define MAXN 8192
#define MAXD 1024
#define MAXJT 64   // N/128

#define M_POS 0.5f
#define M_NEG_SIM 0.1f
#define LAM_NEG 1.0f

// ---------------------------------------------------------------------------
// Device scratch (allocation-free rule: __device__ globals)
// ---------------------------------------------------------------------------
__device__ __align__(16) unsigned char g_cb8[MAXN * MAXD];  // e4m3 codebook (8MB)
__device__ float g_sq[MAXN];
__device__ float g_invn[MAXN];
__device__ float g_pos_part[MAXJT * MAXN];
__device__ float g_neg_part[MAXJT * MAXN];
__device__ float g_per_row[MAXN];
__device__ int   g_valid[MAXN];

// ---------------------------------------------------------------------------
// PTX helpers
// ---------------------------------------------------------------------------
__device__ __forceinline__ uint32_t smem_u32(const void* p) {
    uint32_t a;
    asm("{ .reg .u64 t; cvta.to.shared.u64 t, %1; cvt.u32.u64 %0, t; }"
        : "=r"(a) : "l"(p));
    return a;
}

__device__ __forceinline__ void cp16(uint32_t dst, const void* src) {
    asm volatile("cp.async.cg.shared.global [%0], [%1], 16;"
                 :: "r"(dst), "l"(src) : "memory");
}
#define CP_COMMIT() asm volatile("cp.async.commit_group;" ::: "memory")

__device__ __forceinline__ void ldm_x4(uint32_t& r0, uint32_t& r1,
                                       uint32_t& r2, uint32_t& r3, uint32_t addr) {
    asm volatile("ldmatrix.sync.aligned.m8n8.x4.shared.b16 {%0,%1,%2,%3}, [%4];"
                 : "=r"(r0), "=r"(r1), "=r"(r2), "=r"(r3) : "r"(addr));
}

// FP8 e4m3 MMA: m16n8k32, fp32 accumulate. Fragment byte layout matches the
// bf16 m16n8k16 pattern (4-byte k-groups per lane), so ldmatrix.b16 loads work.
__device__ __forceinline__ void mma_fp8(float* c, uint32_t a0, uint32_t a1,
                                        uint32_t a2, uint32_t a3,
                                        uint32_t b0, uint32_t b1) {
    asm volatile(
        "mma.sync.aligned.m16n8k32.row.col.f32.e4m3.e4m3.f32 "
        "{%0,%1,%2,%3}, {%4,%5,%6,%7}, {%8,%9}, {%0,%1,%2,%3};"
        : "+f"(c[0]), "+f"(c[1]), "+f"(c[2]), "+f"(c[3])
        : "r"(a0), "r"(a1), "r"(a2), "r"(a3), "r"(b0), "r"(b1));
}

// XOR-swizzled tile layout: 128 logical rows x 64 B (BK=64 fp8) packed as
// 64 physical rows x 128B.  off0 = (r>>1)*128 + (r&1)*64 + kbyte;
// phys = off0 ^ ((off0>>3)&0x70).  Conflict-free for cp.async stores AND
// ldmatrix reads (verified against the 32-bank model).
__device__ __forceinline__ uint32_t tile_off(int r, int kbyte) {
    uint32_t off0 = ((uint32_t)(r >> 1) << 7) + ((uint32_t)(r & 1) << 6)
                  + (uint32_t)kbyte;
    return off0 ^ ((off0 >> 3) & 0x70);
}

// SMEM layout (bytes, relative to dynamic smem base). 5-stage pipeline.
#define TILE_BYTES  8192u             // 64 * 128
#define BUF_BYTES   16384u            // A + B per stage
#define NSTAGE      5
#define OFF_META    81920u            // after 5 stages
#define OFF_SS      (OFF_META + 0u)     // int[128]   starts of i-block
#define OFF_SE      (OFF_META + 512u)   // int[128]   ends of i-block
#define OFF_SQI     (OFF_META + 1024u)  // float[128]
#define OFF_INVI    (OFF_META + 1536u)  // float[128]
#define OFF_SQJ     (OFF_META + 2048u)  // float[128]
#define OFF_INVJ    (OFF_META + 2560u)  // float[128]
#define OFF_COMBP   (OFF_META + 3072u)  // float[128]
#define OFF_COMBN   (OFF_META + 3584u)  // float[128]
#define OFF_SS2     (OFF_META + 4096u)  // int[128]   starts of j-block
#define OFF_SE2     (OFF_META + 4608u)  // int[128]   ends of j-block
#define OFF_CTP     (OFF_META + 5120u)  // float[128] transpose pos accum
#define OFF_CTN     (OFF_META + 5632u)  // float[128] transpose neg accum
#define SMEM_TOTAL  (OFF_META + 6144u)

// ---------------------------------------------------------------------------
// Pass 0+1 fused: fp32 -> e4m3 conversion AND per-row norms in one read pass
// ---------------------------------------------------------------------------
__global__ __launch_bounds__(256) void k_prep(const float* __restrict__ cb,
                                              int N, int d) {
    int row = blockIdx.x;
    if (row >= N) return;
    const float* p = cb + (size_t)row * d;
    unsigned char* o = g_cb8 + (size_t)row * d;
    float s = 0.f;
    for (int c = threadIdx.x * 8; c < d; c += blockDim.x * 8) {
        float4 v0 = *(const float4*)(p + c);
        float4 v1 = *(const float4*)(p + c + 4);
        s = fmaf(v0.x, v0.x, s);  s = fmaf(v0.y, v0.y, s);
        s = fmaf(v0.z, v0.z, s);  s = fmaf(v0.w, v0.w, s);
        s = fmaf(v1.x, v1.x, s);  s = fmaf(v1.y, v1.y, s);
        s = fmaf(v1.z, v1.z, s);  s = fmaf(v1.w, v1.w, s);
        uint32_t q0 = (uint32_t)__nv_cvt_float2_to_fp8x2(
                          make_float2(v0.x, v0.y), __NV_SATFINITE, __NV_E4M3);
        uint32_t q1 = (uint32_t)__nv_cvt_float2_to_fp8x2(
                          make_float2(v0.z, v0.w), __NV_SATFINITE, __NV_E4M3);
        uint32_t q2 = (uint32_t)__nv_cvt_float2_to_fp8x2(
                          make_float2(v1.x, v1.y), __NV_SATFINITE, __NV_E4M3);
        uint32_t q3 = (uint32_t)__nv_cvt_float2_to_fp8x2(
                          make_float2(v1.z, v1.w), __NV_SATFINITE, __NV_E4M3);
        uint2 w;
        w.x = q0 | (q1 << 16);
        w.y = q2 | (q3 << 16);
        *(uint2*)(o + c) = w;
    }
    #pragma unroll
    for (int off = 16; off; off >>= 1) s += __shfl_down_sync(0xffffffffu, s, off);
    __shared__ float sh[8];
    if ((threadIdx.x & 31) == 0) sh[threadIdx.x >> 5] = s;
    __syncthreads();
    if (threadIdx.x < 8) {
        float v = sh[threadIdx.x];
        #pragma unroll
        for (int off = 4; off; off >>= 1) v += __shfl_down_sync(0xffu, v, off);
        if (threadIdx.x == 0) {
            g_sq[row]   = v;
            g_invn[row] = rsqrtf(fmaxf(v, 1e-30f));
        }
    }
}

// ---------------------------------------------------------------------------
// Pass 2: FP8 MMA Gram tile 128x128, SYMMETRIC, 1D triangular grid,
// 5-stage cp.async pipeline, MERGED single-pass dual-orientation epilogue.
// ---------------------------------------------------------------------------
__global__ __launch_bounds__(256, 2) void k_main(
    const int* __restrict__ starts,
    const int* __restrict__ ends,
    const int* __restrict__ pmaxi,
    int N, int d, int njt)
{
    // map linear block id -> upper-triangular (it, jt), it <= jt
    int bidx = blockIdx.x;
    float nf = (float)njt + 0.5f;
    int it = (int)(nf - sqrtf(fmaxf(nf * nf - 2.0f * (float)bidx, 0.f)));
    while (it > 0 && it * njt - it * (it - 1) / 2 > bidx) it--;
    while ((it + 1) * njt - (it + 1) * it / 2 <= bidx) it++;
    const int jt = it + (bidx - (it * njt - it * (it - 1) / 2));

    extern __shared__ __align__(128) char smc[];
    const uint32_t sb = smem_u32(smc);

    const int tid    = threadIdx.x;
    const int wid    = tid >> 5;
    const int lane   = tid & 31;
    const int warp_m = wid & 3;   // rows warp_m*32
    const int warp_n = wid >> 2;  // cols warp_n*64
    const int i0     = it * 128;
    const int j0     = jt * 128;
    const bool diag  = (it == jt);

    // stage per-row/col metadata; zero transpose accumulators
    {
        int t = tid & 127;
        if (tid < 128) {
            int gi = i0 + t;
            ((int*)(smc + OFF_SS))[t]     = starts[gi];
            ((int*)(smc + OFF_SE))[t]     = ends[gi];
            ((float*)(smc + OFF_SQI))[t]  = g_sq[gi];
            ((float*)(smc + OFF_INVI))[t] = g_invn[gi];
            ((float*)(smc + OFF_CTP))[t]  = 0.f;
        } else {
            int gj = j0 + t;
            ((float*)(smc + OFF_SQJ))[t]  = g_sq[gj];
            ((float*)(smc + OFF_INVJ))[t] = g_invn[gj];
            ((int*)(smc + OFF_SS2))[t]    = starts[gj];
            ((int*)(smc + OFF_SE2))[t]    = ends[gj];
            ((float*)(smc + OFF_CTN))[t]  = 0.f;
        }
    }

    float acc[2][8][4];
    #pragma unroll
    for (int m = 0; m < 2; m++)
        #pragma unroll
        for (int g = 0; g < 8; g++)
            #pragma unroll
            for (int e = 0; e < 4; e++) acc[m][g][e] = 0.f;

    const unsigned char* __restrict__ cb8 = g_cb8;

    // BK=64 fp8 elements = 64 bytes/row. 128 rows x 4 x 16B = 512 segs/tile.
    auto load_chunk = [&](int c, int b) {
        const int k0 = c * 64;
        const uint32_t ab = sb + (uint32_t)b * BUF_BYTES;
        const uint32_t bbse = ab + TILE_BYTES;
        #pragma unroll
        for (int t = 0; t < 2; t++) {
            int seg = tid + t * 256;
            int r = seg >> 2, qc = seg & 3;
            cp16(ab + tile_off(r, qc * 16),
                 cb8 + (size_t)(i0 + r) * d + k0 + qc * 16);
        }
        #pragma unroll
        for (int t = 0; t < 2; t++) {
            int seg = tid + t * 256;
            int r = seg >> 2, qc = seg & 3;
            cp16(bbse + tile_off(r, qc * 16),
                 cb8 + (size_t)(j0 + r) * d + k0 + qc * 16);
        }
        CP_COMMIT();
    };

    const int NC = d >> 6;   // chunks of BK=64
    load_chunk(0, 0);
    if (NC > 1) load_chunk(1, 1);
    if (NC > 2) load_chunk(2, 2);
    if (NC > 3) load_chunk(3, 3);

    for (int c = 0; c < NC; c++) {
        // ensure chunk c complete (pending = #chunks issued beyond c)
        if (c + 3 < NC)      asm volatile("cp.async.wait_group 3;" ::: "memory");
        else if (c + 2 < NC) asm volatile("cp.async.wait_group 2;" ::: "memory");
        else if (c + 1 < NC) asm volatile("cp.async.wait_group 1;" ::: "memory");
        else                 asm volatile("cp.async.wait_group 0;" ::: "memory");
        // single barrier: stage-c data visible; all warps done with stage c-1,
        // so buffer (c+4)%5 == (c-1)%5 is free for refill.
        __syncthreads();
        if (c + 4 < NC) load_chunk(c + 4, (c + 4) % NSTAGE);

        const uint32_t Ab = sb + (uint32_t)(c % NSTAGE) * BUF_BYTES;
        const uint32_t Bb = Ab + TILE_BYTES;

        #pragma unroll
        for (int ks = 0; ks < 2; ks++) {
            const int kb = ks * 32;   // byte offset of this K=32(e4m3) slice
            uint32_t a[2][4];
            #pragma unroll
            for (int m = 0; m < 2; m++) {
                int row = warp_m * 32 + m * 16 + (lane & 15);
                uint32_t addr = Ab + tile_off(row, kb + (lane >> 4) * 16);
                ldm_x4(a[m][0], a[m][1], a[m][2], a[m][3], addr);
            }
            uint32_t bf[4][4];
            #pragma unroll
            for (int g = 0; g < 4; g++) {
                int sel = lane >> 3;
                int row = warp_n * 64 + g * 16 + (sel & 1) * 8 + (lane & 7);
                uint32_t addr = Bb + tile_off(row, kb + (sel >> 1) * 16);
                ldm_x4(bf[g][0], bf[g][1], bf[g][2], bf[g][3], addr);
            }
            #pragma unroll
            for (int m = 0; m < 2; m++)
                #pragma unroll
                for (int g = 0; g < 4; g++) {
                    mma_fp8(acc[m][2 * g],     a[m][0], a[m][1], a[m][2], a[m][3],
                            bf[g][0], bf[g][2]);
                    mma_fp8(acc[m][2 * g + 1], a[m][0], a[m][1], a[m][2], a[m][3],
                            bf[g][1], bf[g][3]);
                }
        }
    }

    // --- MERGED epilogue: one pass computes symmetric term values once and
    // routes them through both orientation masks (row = i-view, col = j-view).
    const int M = min(N, pmaxi[0] + 1);
    const int rq = lane >> 2;
    const int cq = lane & 3;

    const int*   sS    = (const int*)(smc + OFF_SS);
    const int*   sE    = (const int*)(smc + OFF_SE);
    const float* sqi_  = (const float*)(smc + OFF_SQI);
    const float* invi_ = (const float*)(smc + OFF_INVI);
    const float* sqj_  = (const float*)(smc + OFF_SQJ);
    const float* invj_ = (const float*)(smc + OFF_INVJ);
    const int*   sS2   = (const int*)(smc + OFF_SS2);
    const int*   sE2   = (const int*)(smc + OFF_SE2);
    float* combP = (float*)(smc + OFF_COMBP);
    float* combN = (float*)(smc + OFF_COMBN);
    float* ctP   = (float*)(smc + OFF_CTP);
    float* ctN   = (float*)(smc + OFF_CTN);

    float pcol[16], ncol[16];
    #pragma unroll
    for (int q = 0; q < 16; q++) { pcol[q] = 0.f; ncol[q] = 0.f; }

    float posL[2][2], negL[2][2];
    #pragma unroll
    for (int m = 0; m < 2; m++) {
        #pragma unroll
        for (int h = 0; h < 2; h++) {
            int rl = warp_m * 32 + m * 16 + h * 8 + rq;
            int gi = i0 + rl;
            int   s_  = sS[rl],   e_   = sE[rl];
            float sqi = sqi_[rl], invi = invi_[rl];
            const bool rowAct = (gi < M);
            float pos = 0.f, neg = 0.f;
            #pragma unroll
            for (int g = 0; g < 8; g++) {
                #pragma unroll
                for (int ee = 0; ee < 2; ee++) {
                    int cl = warp_n * 64 + g * 8 + cq * 2 + ee;
                    int gj = j0 + cl;
                    int q_ = g * 2 + ee;
                    float dot = acc[m][g][h * 2 + ee];
                    bool in_i = (gj >= s_) && (gj <= e_) && (gj != gi);
                    bool in_j = (gi >= sS2[cl]) && (gi <= sE2[cl]) && (gj != gi);
                    float posv = 0.f, negv = 0.f;
                    if (in_i || in_j) {              // rare: positive pairs
                        float d2 = fmaxf(sqi + sqj_[cl] - 2.f * dot, 0.f);
                        float t  = sqrtf(d2) - M_POS;
                        if (t > 0.f) posv = t * t;
                    }
                    if (!(in_i && in_j)) {           // common: negative pairs
                        float cs = fminf(1.f, fmaxf(-1.f, dot * invi * invj_[cl]));
                        float a  = fabsf(cs) - M_NEG_SIM;
                        if (a > 0.f) negv = a * a;
                    }
                    if (rowAct) {
                        pos += in_i ? posv : 0.f;
                        neg += in_i ? 0.f : negv;
                    }
                    if (!diag && gj < M) {
                        pcol[q_] += in_j ? posv : 0.f;
                        ncol[q_] += in_j ? 0.f : negv;
                    }
                }
            }
            pos += __shfl_xor_sync(0xffffffffu, pos, 1);
            pos += __shfl_xor_sync(0xffffffffu, pos, 2);
            neg += __shfl_xor_sync(0xffffffffu, neg, 1);
            neg += __shfl_xor_sync(0xffffffffu, neg, 2);
            if (cq == 0 && warp_n == 1) { combP[rl] = pos; combN[rl] = neg; }
            posL[m][h] = pos;  negL[m][h] = neg;
        }
    }
    __syncthreads();
    if (warp_n == 0 && cq == 0) {
        #pragma unroll
        for (int m = 0; m < 2; m++)
            #pragma unroll
            for (int h = 0; h < 2; h++) {
                int rl = warp_m * 32 + m * 16 + h * 8 + rq;
                int gi = i0 + rl;
                g_pos_part[jt * N + gi] = posL[m][h] + combP[rl];
                g_neg_part[jt * N + gi] = negL[m][h] + combN[rl];
            }
    }

    // --- column-orientation reduction + write (off-diagonal only) ---
    if (!diag) {
        #pragma unroll
        for (int q = 0; q < 16; q++) {
            #pragma unroll
            for (int off = 4; off <= 16; off <<= 1) {
                pcol[q] += __shfl_xor_sync(0xffffffffu, pcol[q], off);
                ncol[q] += __shfl_xor_sync(0xffffffffu, ncol[q], off);
            }
        }
        if (rq == 0) {
            #pragma unroll
            for (int g = 0; g < 8; g++) {
                #pragma unroll
                for (int ee = 0; ee < 2; ee++) {
                    int cl = warp_n * 64 + g * 8 + cq * 2 + ee;
                    atomicAdd(&ctP[cl], pcol[g * 2 + ee]);
                    atomicAdd(&ctN[cl], ncol[g * 2 + ee]);
                }
            }
        }
        __syncthreads();
        if (tid < 128) {
            int gj = j0 + tid;
            g_pos_part[it * N + gj] = ctP[tid];
            g_neg_part[it * N + gj] = ctN[tid];
        }
    }
}

// ---------------------------------------------------------------------------
// Pass 3: per-row combine with analytic counts (unrolled partial reduction)
// ---------------------------------------------------------------------------
__global__ void k_rowsum(const int* __restrict__ starts,
                         const int* __restrict__ ends,
                         const int* __restrict__ pmaxi,
                         int N, int njt) {
    int i = blockIdx.x * blockDim.x + threadIdx.x;
    if (i >= N) return;
    int M = min(N, pmaxi[0] + 1);
    float ps = 0.f, ns = 0.f;
    int t = 0;
    for (; t + 8 <= njt; t += 8) {
        float p0 = g_pos_part[(t + 0) * N + i], n0 = g_neg_part[(t + 0) * N + i];
        float p1 = g_pos_part[(t + 1) * N + i], n1 = g_neg_part[(t + 1) * N + i];
        float p2 = g_pos_part[(t + 2) * N + i], n2 = g_neg_part[(t + 2) * N + i];
        float p3 = g_pos_part[(t + 3) * N + i], n3 = g_neg_part[(t + 3) * N + i];
        float p4 = g_pos_part[(t + 4) * N + i], n4 = g_neg_part[(t + 4) * N + i];
        float p5 = g_pos_part[(t + 5) * N + i], n5 = g_neg_part[(t + 5) * N + i];
        float p6 = g_pos_part[(t + 6) * N + i], n6 = g_neg_part[(t + 6) * N + i];
        float p7 = g_pos_part[(t + 7) * N + i], n7 = g_neg_part[(t + 7) * N + i];
        ps += ((p0 + p1) + (p2 + p3)) + ((p4 + p5) + (p6 + p7));
        ns += ((n0 + n1) + (n2 + n3)) + ((n4 + n5) + (n6 + n7));
    }
    for (; t < njt; t++) {
        ps += g_pos_part[t * N + i];
        ns += g_neg_part[t * N + i];
    }
    int s = starts[i], e = ends[i];
    int lo = s < 0 ? 0 : s;
    int hi = e > N - 1 ? N - 1 : e;
    int cin = hi - lo + 1; if (cin < 0) cin = 0;
    int iin = (i >= s && i <= e) ? 1 : 0;
    int pc = cin - iin;
    int nc = N - cin + iin;
    bool valid = (i < M) && (pc > 0) && (nc > 0);
    float pr = 0.f;
    if (valid)
        pr = ps / (float)(pc < 1 ? 1 : pc) + LAM_NEG * ns / (float)(nc < 1 ? 1 : nc);
    g_per_row[i] = pr;
    g_valid[i]   = valid ? 1 : 0;
}

// ---------------------------------------------------------------------------
// Pass 4: final scalar reduction (1024 threads, 1 block)
// ---------------------------------------------------------------------------
__global__ void k_final(float* __restrict__ out, int N) {
    float s = 0.f; int c = 0;
    for (int i = threadIdx.x; i < N; i += blockDim.x) {
        s += g_per_row[i];
        c += g_valid[i];
    }
    #pragma unroll
    for (int off = 16; off; off >>= 1) {
        s += __shfl_down_sync(0xffffffffu, s, off);
        c += __shfl_down_sync(0xffffffffu, c, off);
    }
    __shared__ float sh[32];
    __shared__ int   shc[32];
    int nw = blockDim.x >> 5;
    if ((threadIdx.x & 31) == 0) { sh[threadIdx.x >> 5] = s; shc[threadIdx.x >> 5] = c; }
    __syncthreads();
    if (threadIdx.x < 32) {
        s = (threadIdx.x < nw) ? sh[threadIdx.x]  : 0.f;
        c = (threadIdx.x < nw) ? shc[threadIdx.x] : 0;
        #pragma unroll
        for (int off = 16; off; off >>= 1) {
            s += __shfl_down_sync(0xffffffffu, s, off);
            c += __shfl_down_sync(0xffffffffu, c, off);
        }
        if (threadIdx.x == 0) out[0] = (c > 0) ? s / (float)c : 0.f;
    }
}

// ---------------------------------------------------------------------------
// Launch
// ---------------------------------------------------------------------------
extern "C" void kernel_launch(void* const* d_in, const int* in_sizes, int n_in,
                              void* d_out, int out_size) {
    const float* cb     = (const float*)d_in[0];
    const int*   starts = (const int*)d_in[1];
    const int*   ends   = (const int*)d_in[2];
    const int*   pmaxi  = (const int*)d_in[3];

    int N = in_sizes[1];             // starts has N elements
    int d = in_sizes[0] / N;         // codebook is N x d

    cudaFuncSetAttribute(k_main, cudaFuncAttributeMaxDynamicSharedMemorySize,
                         (int)SMEM_TOTAL);

    k_prep<<<N, 256>>>(cb, N, d);

    int njt = N / 128;
    int ntri = njt * (njt + 1) / 2;
    k_main<<<ntri, 256, SMEM_TOTAL>>>(starts, ends, pmaxi, N, d, njt);

    k_rowsum<<<(N + 255) / 256, 256>>>(starts, ends, pmaxi, N, njt);
    k_final<<<1, 1024>>>((float*)d_out, N);
}

// round 13
// speedup vs baseline: 1.0721x; 1.0721x over previous
#include <cuda_runtime.h>
#include <cuda_bf16.h>
#include <cuda_fp8.h>
#include <math.h>
#include <stdint.h>

// Fixed problem envelope (dataset: N=8192, d=1024). Requires N%128==0, d%64==0.
#define MAXN 8192
#define MAXD 1024
#define MAXJT 64   // N/128

#define M_POS 0.5f
#define M_NEG_SIM 0.1f
#define LAM_NEG 1.0f

// ---------------------------------------------------------------------------
// Device scratch (allocation-free rule: __device__ globals)
// ---------------------------------------------------------------------------
__device__ __align__(16) unsigned char g_cb8[MAXN * MAXD];  // e4m3 codebook (8MB)
__device__ float g_sq[MAXN];
__device__ float g_invn[MAXN];
__device__ float g_pos_part[MAXJT * MAXN];
__device__ float g_neg_part[MAXJT * MAXN];
__device__ float g_tot;
__device__ int   g_cnt;

// ---------------------------------------------------------------------------
// PTX helpers
// ---------------------------------------------------------------------------
__device__ __forceinline__ uint32_t smem_u32(const void* p) {
    uint32_t a;
    asm("{ .reg .u64 t; cvta.to.shared.u64 t, %1; cvt.u32.u64 %0, t; }"
        : "=r"(a) : "l"(p));
    return a;
}

__device__ __forceinline__ void cp16(uint32_t dst, const void* src) {
    asm volatile("cp.async.cg.shared.global [%0], [%1], 16;"
                 :: "r"(dst), "l"(src) : "memory");
}
#define CP_COMMIT() asm volatile("cp.async.commit_group;" ::: "memory")

__device__ __forceinline__ void ldm_x4(uint32_t& r0, uint32_t& r1,
                                       uint32_t& r2, uint32_t& r3, uint32_t addr) {
    asm volatile("ldmatrix.sync.aligned.m8n8.x4.shared.b16 {%0,%1,%2,%3}, [%4];"
                 : "=r"(r0), "=r"(r1), "=r"(r2), "=r"(r3) : "r"(addr));
}

// FP8 e4m3 MMA: m16n8k32, fp32 accumulate. Fragment byte layout matches the
// bf16 m16n8k16 pattern (4-byte k-groups per lane), so ldmatrix.b16 loads work.
__device__ __forceinline__ void mma_fp8(float* c, uint32_t a0, uint32_t a1,
                                        uint32_t a2, uint32_t a3,
                                        uint32_t b0, uint32_t b1) {
    asm volatile(
        "mma.sync.aligned.m16n8k32.row.col.f32.e4m3.e4m3.f32 "
        "{%0,%1,%2,%3}, {%4,%5,%6,%7}, {%8,%9}, {%0,%1,%2,%3};"
        : "+f"(c[0]), "+f"(c[1]), "+f"(c[2]), "+f"(c[3])
        : "r"(a0), "r"(a1), "r"(a2), "r"(a3), "r"(b0), "r"(b1));
}

// XOR-swizzled tile layout: 128 logical rows x 64 B (BK=64 fp8) packed as
// 64 physical rows x 128B.  off0 = (r>>1)*128 + (r&1)*64 + kbyte;
// phys = off0 ^ ((off0>>3)&0x70).  Conflict-free for cp.async stores AND
// ldmatrix reads (verified against the 32-bank model).
__device__ __forceinline__ uint32_t tile_off(int r, int kbyte) {
    uint32_t off0 = ((uint32_t)(r >> 1) << 7) + ((uint32_t)(r & 1) << 6)
                  + (uint32_t)kbyte;
    return off0 ^ ((off0 >> 3) & 0x70);
}

// SMEM layout (bytes, relative to dynamic smem base). 5-stage pipeline.
#define TILE_BYTES  8192u             // 64 * 128
#define BUF_BYTES   16384u            // A + B per stage
#define NSTAGE      5
#define OFF_META    81920u            // after 5 stages
#define OFF_SS      (OFF_META + 0u)     // int[128]   starts of i-block
#define OFF_SE      (OFF_META + 512u)   // int[128]   ends of i-block
#define OFF_SQI     (OFF_META + 1024u)  // float[128]
#define OFF_INVI    (OFF_META + 1536u)  // float[128]
#define OFF_SQJ     (OFF_META + 2048u)  // float[128]
#define OFF_INVJ    (OFF_META + 2560u)  // float[128]
#define OFF_COMBP   (OFF_META + 3072u)  // float[128]
#define OFF_COMBN   (OFF_META + 3584u)  // float[128]
#define OFF_SS2     (OFF_META + 4096u)  // int[128]   starts of j-block
#define OFF_SE2     (OFF_META + 4608u)  // int[128]   ends of j-block
#define OFF_CTP     (OFF_META + 5120u)  // float[128] transpose pos accum
#define OFF_CTN     (OFF_META + 5632u)  // float[128] transpose neg accum
#define SMEM_TOTAL  (OFF_META + 6144u)

// ---------------------------------------------------------------------------
// Pass 0+1 fused: fp32 -> e4m3 conversion + per-row norms, WARP-PER-ROW
// (8 rows per 256-thread block). Also zeroes the global loss accumulators.
// ---------------------------------------------------------------------------
__global__ __launch_bounds__(256) void k_prep(const float* __restrict__ cb,
                                              int N, int d) {
    if (blockIdx.x == 0 && threadIdx.x == 0) { g_tot = 0.f; g_cnt = 0; }
    int wid  = threadIdx.x >> 5;
    int lane = threadIdx.x & 31;
    int row  = blockIdx.x * 8 + wid;
    if (row >= N) return;
    const float* p = cb + (size_t)row * d;
    unsigned char* o = g_cb8 + (size_t)row * d;
    float s = 0.f;
    for (int c = lane * 8; c < d; c += 32 * 8) {
        float4 v0 = *(const float4*)(p + c);
        float4 v1 = *(const float4*)(p + c + 4);
        s = fmaf(v0.x, v0.x, s);  s = fmaf(v0.y, v0.y, s);
        s = fmaf(v0.z, v0.z, s);  s = fmaf(v0.w, v0.w, s);
        s = fmaf(v1.x, v1.x, s);  s = fmaf(v1.y, v1.y, s);
        s = fmaf(v1.z, v1.z, s);  s = fmaf(v1.w, v1.w, s);
        uint32_t q0 = (uint32_t)__nv_cvt_float2_to_fp8x2(
                          make_float2(v0.x, v0.y), __NV_SATFINITE, __NV_E4M3);
        uint32_t q1 = (uint32_t)__nv_cvt_float2_to_fp8x2(
                          make_float2(v0.z, v0.w), __NV_SATFINITE, __NV_E4M3);
        uint32_t q2 = (uint32_t)__nv_cvt_float2_to_fp8x2(
                          make_float2(v1.x, v1.y), __NV_SATFINITE, __NV_E4M3);
        uint32_t q3 = (uint32_t)__nv_cvt_float2_to_fp8x2(
                          make_float2(v1.z, v1.w), __NV_SATFINITE, __NV_E4M3);
        uint2 w;
        w.x = q0 | (q1 << 16);
        w.y = q2 | (q3 << 16);
        *(uint2*)(o + c) = w;
    }
    #pragma unroll
    for (int off = 16; off; off >>= 1) s += __shfl_down_sync(0xffffffffu, s, off);
    if (lane == 0) {
        g_sq[row]   = s;
        g_invn[row] = rsqrtf(fmaxf(s, 1e-30f));
    }
}

// ---------------------------------------------------------------------------
// Pass 2: FP8 MMA Gram tile 128x128, SYMMETRIC, 1D triangular grid,
// 5-stage cp.async pipeline, XOR-swizzled conflict-free SMEM, 2 CTAs/SM.
// (Byte-identical mainloop/epilogue to the 256.5us best configuration.)
// ---------------------------------------------------------------------------
__global__ __launch_bounds__(256, 2) void k_main(
    const int* __restrict__ starts,
    const int* __restrict__ ends,
    const int* __restrict__ pmaxi,
    int N, int d, int njt)
{
    // map linear block id -> upper-triangular (it, jt), it <= jt
    int bidx = blockIdx.x;
    float nf = (float)njt + 0.5f;
    int it = (int)(nf - sqrtf(fmaxf(nf * nf - 2.0f * (float)bidx, 0.f)));
    while (it > 0 && it * njt - it * (it - 1) / 2 > bidx) it--;
    while ((it + 1) * njt - (it + 1) * it / 2 <= bidx) it++;
    const int jt = it + (bidx - (it * njt - it * (it - 1) / 2));

    extern __shared__ __align__(128) char smc[];
    const uint32_t sb = smem_u32(smc);

    const int tid    = threadIdx.x;
    const int wid    = tid >> 5;
    const int lane   = tid & 31;
    const int warp_m = wid & 3;   // rows warp_m*32
    const int warp_n = wid >> 2;  // cols warp_n*64
    const int i0     = it * 128;
    const int j0     = jt * 128;
    const bool diag  = (it == jt);

    // stage per-row/col metadata; zero transpose accumulators
    {
        int t = tid & 127;
        if (tid < 128) {
            int gi = i0 + t;
            ((int*)(smc + OFF_SS))[t]     = starts[gi];
            ((int*)(smc + OFF_SE))[t]     = ends[gi];
            ((float*)(smc + OFF_SQI))[t]  = g_sq[gi];
            ((float*)(smc + OFF_INVI))[t] = g_invn[gi];
            ((float*)(smc + OFF_CTP))[t]  = 0.f;
        } else {
            int gj = j0 + t;
            ((float*)(smc + OFF_SQJ))[t]  = g_sq[gj];
            ((float*)(smc + OFF_INVJ))[t] = g_invn[gj];
            ((int*)(smc + OFF_SS2))[t]    = starts[gj];
            ((int*)(smc + OFF_SE2))[t]    = ends[gj];
            ((float*)(smc + OFF_CTN))[t]  = 0.f;
        }
    }

    float acc[2][8][4];
    #pragma unroll
    for (int m = 0; m < 2; m++)
        #pragma unroll
        for (int g = 0; g < 8; g++)
            #pragma unroll
            for (int e = 0; e < 4; e++) acc[m][g][e] = 0.f;

    const unsigned char* __restrict__ cb8 = g_cb8;

    // BK=64 fp8 elements = 64 bytes/row. 128 rows x 4 x 16B = 512 segs/tile.
    auto load_chunk = [&](int c, int b) {
        const int k0 = c * 64;
        const uint32_t ab = sb + (uint32_t)b * BUF_BYTES;
        const uint32_t bbse = ab + TILE_BYTES;
        #pragma unroll
        for (int t = 0; t < 2; t++) {
            int seg = tid + t * 256;
            int r = seg >> 2, qc = seg & 3;
            cp16(ab + tile_off(r, qc * 16),
                 cb8 + (size_t)(i0 + r) * d + k0 + qc * 16);
        }
        #pragma unroll
        for (int t = 0; t < 2; t++) {
            int seg = tid + t * 256;
            int r = seg >> 2, qc = seg & 3;
            cp16(bbse + tile_off(r, qc * 16),
                 cb8 + (size_t)(j0 + r) * d + k0 + qc * 16);
        }
        CP_COMMIT();
    };

    const int NC = d >> 6;   // chunks of BK=64
    load_chunk(0, 0);
    if (NC > 1) load_chunk(1, 1);
    if (NC > 2) load_chunk(2, 2);
    if (NC > 3) load_chunk(3, 3);

    for (int c = 0; c < NC; c++) {
        // ensure chunk c complete (pending = #chunks issued beyond c)
        if (c + 3 < NC)      asm volatile("cp.async.wait_group 3;" ::: "memory");
        else if (c + 2 < NC) asm volatile("cp.async.wait_group 2;" ::: "memory");
        else if (c + 1 < NC) asm volatile("cp.async.wait_group 1;" ::: "memory");
        else                 asm volatile("cp.async.wait_group 0;" ::: "memory");
        // single barrier: stage-c data visible; all warps done with stage c-1,
        // so buffer (c+4)%5 == (c-1)%5 is free for refill.
        __syncthreads();
        if (c + 4 < NC) load_chunk(c + 4, (c + 4) % NSTAGE);

        const uint32_t Ab = sb + (uint32_t)(c % NSTAGE) * BUF_BYTES;
        const uint32_t Bb = Ab + TILE_BYTES;

        #pragma unroll
        for (int ks = 0; ks < 2; ks++) {
            const int kb = ks * 32;   // byte offset of this K=32(e4m3) slice
            uint32_t a[2][4];
            #pragma unroll
            for (int m = 0; m < 2; m++) {
                int row = warp_m * 32 + m * 16 + (lane & 15);
                uint32_t addr = Ab + tile_off(row, kb + (lane >> 4) * 16);
                ldm_x4(a[m][0], a[m][1], a[m][2], a[m][3], addr);
            }
            uint32_t bf[4][4];
            #pragma unroll
            for (int g = 0; g < 4; g++) {
                int sel = lane >> 3;
                int row = warp_n * 64 + g * 16 + (sel & 1) * 8 + (lane & 7);
                uint32_t addr = Bb + tile_off(row, kb + (sel >> 1) * 16);
                ldm_x4(bf[g][0], bf[g][1], bf[g][2], bf[g][3], addr);
            }
            #pragma unroll
            for (int m = 0; m < 2; m++)
                #pragma unroll
                for (int g = 0; g < 4; g++) {
                    mma_fp8(acc[m][2 * g],     a[m][0], a[m][1], a[m][2], a[m][3],
                            bf[g][0], bf[g][2]);
                    mma_fp8(acc[m][2 * g + 1], a[m][0], a[m][1], a[m][2], a[m][3],
                            bf[g][1], bf[g][3]);
                }
        }
    }

    // --- epilogue (normal orientation: rows = i-block, partial slot jt) ---
    const int M = min(N, pmaxi[0] + 1);
    const int rq = lane >> 2;
    const int cq = lane & 3;

    const int*   sS    = (const int*)(smc + OFF_SS);
    const int*   sE    = (const int*)(smc + OFF_SE);
    const float* sqi_  = (const float*)(smc + OFF_SQI);
    const float* invi_ = (const float*)(smc + OFF_INVI);
    const float* sqj_  = (const float*)(smc + OFF_SQJ);
    const float* invj_ = (const float*)(smc + OFF_INVJ);
    const int*   sS2   = (const int*)(smc + OFF_SS2);
    const int*   sE2   = (const int*)(smc + OFF_SE2);
    float* combP = (float*)(smc + OFF_COMBP);
    float* combN = (float*)(smc + OFF_COMBN);
    float* ctP   = (float*)(smc + OFF_CTP);
    float* ctN   = (float*)(smc + OFF_CTN);

    float posL[2][2], negL[2][2];
    #pragma unroll
    for (int m = 0; m < 2; m++) {
        #pragma unroll
        for (int h = 0; h < 2; h++) {
            int rl = warp_m * 32 + m * 16 + h * 8 + rq;
            int gi = i0 + rl;
            float pos = 0.f, neg = 0.f;
            if (gi < M) {
                int   s_  = sS[rl],   e_   = sE[rl];
                float sqi = sqi_[rl], invi = invi_[rl];
                #pragma unroll
                for (int g = 0; g < 8; g++) {
                    #pragma unroll
                    for (int ee = 0; ee < 2; ee++) {
                        int cl = warp_n * 64 + g * 8 + cq * 2 + ee;
                        int gj = j0 + cl;
                        float dot = acc[m][g][h * 2 + ee];
                        bool pm = (gj >= s_) && (gj <= e_) && (gj != gi);
                        if (pm) {
                            float d2 = fmaxf(sqi + sqj_[cl] - 2.f * dot, 0.f);
                            float t  = sqrtf(d2) - M_POS;
                            if (t > 0.f) pos = fmaf(t, t, pos);
                        } else {
                            float cs = fminf(1.f, fmaxf(-1.f, dot * invi * invj_[cl]));
                            float a  = fabsf(cs) - M_NEG_SIM;
                            if (a > 0.f) neg = fmaf(a, a, neg);
                        }
                    }
                }
            }
            pos += __shfl_xor_sync(0xffffffffu, pos, 1);
            pos += __shfl_xor_sync(0xffffffffu, pos, 2);
            neg += __shfl_xor_sync(0xffffffffu, neg, 1);
            neg += __shfl_xor_sync(0xffffffffu, neg, 2);
            if (cq == 0 && warp_n == 1) { combP[rl] = pos; combN[rl] = neg; }
            posL[m][h] = pos;  negL[m][h] = neg;
        }
    }
    __syncthreads();
    if (warp_n == 0 && cq == 0) {
        #pragma unroll
        for (int m = 0; m < 2; m++)
            #pragma unroll
            for (int h = 0; h < 2; h++) {
                int rl = warp_m * 32 + m * 16 + h * 8 + rq;
                int gi = i0 + rl;
                g_pos_part[jt * N + gi] = posL[m][h] + combP[rl];
                g_neg_part[jt * N + gi] = negL[m][h] + combN[rl];
            }
    }

    // --- transposed epilogue (off-diagonal only): rows = j-block, slot it ---
    if (!diag) {
        float pcol[16], ncol[16];
        #pragma unroll
        for (int q = 0; q < 16; q++) { pcol[q] = 0.f; ncol[q] = 0.f; }

        #pragma unroll
        for (int m = 0; m < 2; m++) {
            #pragma unroll
            for (int h = 0; h < 2; h++) {
                int rl = warp_m * 32 + m * 16 + h * 8 + rq;
                float sqc  = sqi_[rl];    // i-row acts as column
                float invc = invi_[rl];
                int gic = i0 + rl;
                #pragma unroll
                for (int g = 0; g < 8; g++) {
                    #pragma unroll
                    for (int ee = 0; ee < 2; ee++) {
                        int cl = warp_n * 64 + g * 8 + cq * 2 + ee;
                        int gjr = j0 + cl;          // j acts as row
                        float dot = acc[m][g][h * 2 + ee];
                        if (gjr < M) {
                            int s_ = sS2[cl], e_ = sE2[cl];
                            int q_ = g * 2 + ee;
                            bool pm = (gic >= s_) && (gic <= e_);
                            if (pm) {
                                float d2 = fmaxf(sqj_[cl] + sqc - 2.f * dot, 0.f);
                                float t  = sqrtf(d2) - M_POS;
                                if (t > 0.f) pcol[q_] = fmaf(t, t, pcol[q_]);
                            } else {
                                float cs = fminf(1.f, fmaxf(-1.f, dot * invj_[cl] * invc));
                                float a  = fabsf(cs) - M_NEG_SIM;
                                if (a > 0.f) ncol[q_] = fmaf(a, a, ncol[q_]);
                            }
                        }
                    }
                }
            }
        }
        #pragma unroll
        for (int q = 0; q < 16; q++) {
            #pragma unroll
            for (int off = 4; off <= 16; off <<= 1) {
                pcol[q] += __shfl_xor_sync(0xffffffffu, pcol[q], off);
                ncol[q] += __shfl_xor_sync(0xffffffffu, ncol[q], off);
            }
        }
        if (rq == 0) {
            #pragma unroll
            for (int g = 0; g < 8; g++) {
                #pragma unroll
                for (int ee = 0; ee < 2; ee++) {
                    int cl = warp_n * 64 + g * 8 + cq * 2 + ee;
                    atomicAdd(&ctP[cl], pcol[g * 2 + ee]);
                    atomicAdd(&ctN[cl], ncol[g * 2 + ee]);
                }
            }
        }
        __syncthreads();
        if (tid < 128) {
            int gj = j0 + tid;
            g_pos_part[it * N + gj] = ctP[tid];
            g_neg_part[it * N + gj] = ctN[tid];
        }
    }
}

// ---------------------------------------------------------------------------
// Pass 3: per-row combine + block reduction + global atomic accumulate
// ---------------------------------------------------------------------------
__global__ void k_rowsum(const int* __restrict__ starts,
                         const int* __restrict__ ends,
                         const int* __restrict__ pmaxi,
                         int N, int njt) {
    int i = blockIdx.x * blockDim.x + threadIdx.x;
    float pr = 0.f;
    int vl = 0;
    if (i < N) {
        int M = min(N, pmaxi[0] + 1);
        float ps = 0.f, ns = 0.f;
        int t = 0;
        for (; t + 8 <= njt; t += 8) {
            float p0 = g_pos_part[(t + 0) * N + i], n0 = g_neg_part[(t + 0) * N + i];
            float p1 = g_pos_part[(t + 1) * N + i], n1 = g_neg_part[(t + 1) * N + i];
            float p2 = g_pos_part[(t + 2) * N + i], n2 = g_neg_part[(t + 2) * N + i];
            float p3 = g_pos_part[(t + 3) * N + i], n3 = g_neg_part[(t + 3) * N + i];
            float p4 = g_pos_part[(t + 4) * N + i], n4 = g_neg_part[(t + 4) * N + i];
            float p5 = g_pos_part[(t + 5) * N + i], n5 = g_neg_part[(t + 5) * N + i];
            float p6 = g_pos_part[(t + 6) * N + i], n6 = g_neg_part[(t + 6) * N + i];
            float p7 = g_pos_part[(t + 7) * N + i], n7 = g_neg_part[(t + 7) * N + i];
            ps += ((p0 + p1) + (p2 + p3)) + ((p4 + p5) + (p6 + p7));
            ns += ((n0 + n1) + (n2 + n3)) + ((n4 + n5) + (n6 + n7));
        }
        for (; t < njt; t++) {
            ps += g_pos_part[t * N + i];
            ns += g_neg_part[t * N + i];
        }
        int s = starts[i], e = ends[i];
        int lo = s < 0 ? 0 : s;
        int hi = e > N - 1 ? N - 1 : e;
        int cin = hi - lo + 1; if (cin < 0) cin = 0;
        int iin = (i >= s && i <= e) ? 1 : 0;
        int pc = cin - iin;
        int nc = N - cin + iin;
        bool valid = (i < M) && (pc > 0) && (nc > 0);
        if (valid) {
            pr = ps / (float)(pc < 1 ? 1 : pc) + LAM_NEG * ns / (float)(nc < 1 ? 1 : nc);
            vl = 1;
        }
    }
    // block reduction
    #pragma unroll
    for (int off = 16; off; off >>= 1) {
        pr += __shfl_down_sync(0xffffffffu, pr, off);
        vl += __shfl_down_sync(0xffffffffu, vl, off);
    }
    __shared__ float sh[8];
    __shared__ int   shc[8];
    if ((threadIdx.x & 31) == 0) { sh[threadIdx.x >> 5] = pr; shc[threadIdx.x >> 5] = vl; }
    __syncthreads();
    if (threadIdx.x < 8) {
        pr = sh[threadIdx.x];  vl = shc[threadIdx.x];
        #pragma unroll
        for (int off = 4; off; off >>= 1) {
            pr += __shfl_down_sync(0xffu, pr, off);
            vl += __shfl_down_sync(0xffu, vl, off);
        }
        if (threadIdx.x == 0) {
            atomicAdd(&g_tot, pr);
            atomicAdd(&g_cnt, vl);
        }
    }
}

// ---------------------------------------------------------------------------
// Pass 4: trivial final division
// ---------------------------------------------------------------------------
__global__ void k_write(float* __restrict__ out) {
    if (threadIdx.x == 0)
        out[0] = (g_cnt > 0) ? g_tot / (float)g_cnt : 0.f;
}

// ---------------------------------------------------------------------------
// Launch
// ---------------------------------------------------------------------------
extern "C" void kernel_launch(void* const* d_in, const int* in_sizes, int n_in,
                              void* d_out, int out_size) {
    const float* cb     = (const float*)d_in[0];
    const int*   starts = (const int*)d_in[1];
    const int*   ends   = (const int*)d_in[2];
    const int*   pmaxi  = (const int*)d_in[3];

    int N = in_sizes[1];             // starts has N elements
    int d = in_sizes[0] / N;         // codebook is N x d

    cudaFuncSetAttribute(k_main, cudaFuncAttributeMaxDynamicSharedMemorySize,
                         (int)SMEM_TOTAL);

    k_prep<<<(N + 7) / 8, 256>>>(cb, N, d);

    int njt = N / 128;
    int ntri = njt * (njt + 1) / 2;
    k_main<<<ntri, 256, SMEM_TOTAL>>>(starts, ends, pmaxi, N, d, njt);

    k_rowsum<<<(N + 255) / 256, 256>>>(starts, ends, pmaxi, N, njt);
    k_write<<<1, 32>>>((float*)d_out);
}

// round 14
// speedup vs baseline: 1.0747x; 1.0024x over previous
#include <cuda_runtime.h>
#include <cuda_bf16.h>
#include <cuda_fp8.h>
#include <math.h>
#include <stdint.h>

// Fixed problem envelope (dataset: N=8192, d=1024). Requires N%128==0, d%64==0.
#define MAXN 8192
#define MAXD 1024
#define MAXJT 64   // N/128

#define M_POS 0.5f
#define M_NEG_SIM 0.1f
#define LAM_NEG 1.0f

// ---------------------------------------------------------------------------
// Device scratch (allocation-free rule: __device__ globals)
// ---------------------------------------------------------------------------
__device__ __align__(16) unsigned char g_cb8[MAXN * MAXD];  // e4m3 codebook (8MB)
__device__ float g_sq[MAXN];
__device__ float g_invn[MAXN];
__device__ float g_pos_part[MAXJT * MAXN];
__device__ float g_neg_part[MAXJT * MAXN];
__device__ float g_tot;
__device__ int   g_cnt;

// ---------------------------------------------------------------------------
// PTX helpers
// ---------------------------------------------------------------------------
__device__ __forceinline__ uint32_t smem_u32(const void* p) {
    uint32_t a;
    asm("{ .reg .u64 t; cvta.to.shared.u64 t, %1; cvt.u32.u64 %0, t; }"
        : "=r"(a) : "l"(p));
    return a;
}

__device__ __forceinline__ void cp16(uint32_t dst, const void* src) {
    asm volatile("cp.async.cg.shared.global [%0], [%1], 16;"
                 :: "r"(dst), "l"(src) : "memory");
}
#define CP_COMMIT() asm volatile("cp.async.commit_group;" ::: "memory")

__device__ __forceinline__ void ldm_x4(uint32_t& r0, uint32_t& r1,
                                       uint32_t& r2, uint32_t& r3, uint32_t addr) {
    asm volatile("ldmatrix.sync.aligned.m8n8.x4.shared.b16 {%0,%1,%2,%3}, [%4];"
                 : "=r"(r0), "=r"(r1), "=r"(r2), "=r"(r3) : "r"(addr));
}

// FP8 e4m3 MMA: m16n8k32, fp32 accumulate. Fragment byte layout matches the
// bf16 m16n8k16 pattern (4-byte k-groups per lane), so ldmatrix.b16 loads work.
__device__ __forceinline__ void mma_fp8(float* c, uint32_t a0, uint32_t a1,
                                        uint32_t a2, uint32_t a3,
                                        uint32_t b0, uint32_t b1) {
    asm volatile(
        "mma.sync.aligned.m16n8k32.row.col.f32.e4m3.e4m3.f32 "
        "{%0,%1,%2,%3}, {%4,%5,%6,%7}, {%8,%9}, {%0,%1,%2,%3};"
        : "+f"(c[0]), "+f"(c[1]), "+f"(c[2]), "+f"(c[3])
        : "r"(a0), "r"(a1), "r"(a2), "r"(a3), "r"(b0), "r"(b1));
}

// XOR-swizzled tile layout: 128 logical rows x 64 B (BK=64 fp8) packed as
// 64 physical rows x 128B.  off0 = (r>>1)*128 + (r&1)*64 + kbyte;
// phys = off0 ^ ((off0>>3)&0x70).  Conflict-free for cp.async stores AND
// ldmatrix reads (verified against the 32-bank model).
__device__ __forceinline__ uint32_t tile_off(int r, int kbyte) {
    uint32_t off0 = ((uint32_t)(r >> 1) << 7) + ((uint32_t)(r & 1) << 6)
                  + (uint32_t)kbyte;
    return off0 ^ ((off0 >> 3) & 0x70);
}

// SMEM layout (bytes, relative to dynamic smem base). 5-stage pipeline.
#define TILE_BYTES  8192u             // 64 * 128
#define BUF_BYTES   16384u            // A + B per stage
#define NSTAGE      5
#define OFF_META    81920u            // after 5 stages
#define OFF_SS      (OFF_META + 0u)     // int[128]   starts of i-block
#define OFF_SE      (OFF_META + 512u)   // int[128]   ends of i-block
#define OFF_SQI     (OFF_META + 1024u)  // float[128]
#define OFF_INVI    (OFF_META + 1536u)  // float[128]
#define OFF_SQJ     (OFF_META + 2048u)  // float[128]
#define OFF_INVJ    (OFF_META + 2560u)  // float[128]
#define OFF_COMBP   (OFF_META + 3072u)  // float[128]
#define OFF_COMBN   (OFF_META + 3584u)  // float[128]
#define OFF_SS2     (OFF_META + 4096u)  // int[128]   starts of j-block
#define OFF_SE2     (OFF_META + 4608u)  // int[128]   ends of j-block
#define OFF_CTP     (OFF_META + 5120u)  // float[128] transpose pos accum
#define OFF_CTN     (OFF_META + 5632u)  // float[128] transpose neg accum
#define SMEM_TOTAL  (OFF_META + 6144u)

// ---------------------------------------------------------------------------
// Pass 0+1 fused: fp32 -> e4m3 conversion + per-row norms, WARP-PER-ROW
// (8 rows per 256-thread block). Also zeroes the global loss accumulators.
// ---------------------------------------------------------------------------
__global__ __launch_bounds__(256) void k_prep(const float* __restrict__ cb,
                                              int N, int d) {
    if (blockIdx.x == 0 && threadIdx.x == 0) { g_tot = 0.f; g_cnt = 0; }
    int wid  = threadIdx.x >> 5;
    int lane = threadIdx.x & 31;
    int row  = blockIdx.x * 8 + wid;
    if (row >= N) return;
    const float* p = cb + (size_t)row * d;
    unsigned char* o = g_cb8 + (size_t)row * d;
    float s = 0.f;
    for (int c = lane * 8; c < d; c += 32 * 8) {
        float4 v0 = *(const float4*)(p + c);
        float4 v1 = *(const float4*)(p + c + 4);
        s = fmaf(v0.x, v0.x, s);  s = fmaf(v0.y, v0.y, s);
        s = fmaf(v0.z, v0.z, s);  s = fmaf(v0.w, v0.w, s);
        s = fmaf(v1.x, v1.x, s);  s = fmaf(v1.y, v1.y, s);
        s = fmaf(v1.z, v1.z, s);  s = fmaf(v1.w, v1.w, s);
        uint32_t q0 = (uint32_t)__nv_cvt_float2_to_fp8x2(
                          make_float2(v0.x, v0.y), __NV_SATFINITE, __NV_E4M3);
        uint32_t q1 = (uint32_t)__nv_cvt_float2_to_fp8x2(
                          make_float2(v0.z, v0.w), __NV_SATFINITE, __NV_E4M3);
        uint32_t q2 = (uint32_t)__nv_cvt_float2_to_fp8x2(
                          make_float2(v1.x, v1.y), __NV_SATFINITE, __NV_E4M3);
        uint32_t q3 = (uint32_t)__nv_cvt_float2_to_fp8x2(
                          make_float2(v1.z, v1.w), __NV_SATFINITE, __NV_E4M3);
        uint2 w;
        w.x = q0 | (q1 << 16);
        w.y = q2 | (q3 << 16);
        *(uint2*)(o + c) = w;
    }
    #pragma unroll
    for (int off = 16; off; off >>= 1) s += __shfl_down_sync(0xffffffffu, s, off);
    if (lane == 0) {
        g_sq[row]   = s;
        g_invn[row] = rsqrtf(fmaxf(s, 1e-30f));
    }
}

// ---------------------------------------------------------------------------
// Pass 2: FP8 MMA Gram tile 128x128, SYMMETRIC, 1D triangular grid,
// 5-stage cp.async pipeline, XOR-swizzled conflict-free SMEM, 2 CTAs/SM.
// (Byte-identical mainloop/epilogue to the 256.5us best configuration.)
// ---------------------------------------------------------------------------
__global__ __launch_bounds__(256, 2) void k_main(
    const int* __restrict__ starts,
    const int* __restrict__ ends,
    const int* __restrict__ pmaxi,
    int N, int d, int njt)
{
    // map linear block id -> upper-triangular (it, jt), it <= jt
    int bidx = blockIdx.x;
    float nf = (float)njt + 0.5f;
    int it = (int)(nf - sqrtf(fmaxf(nf * nf - 2.0f * (float)bidx, 0.f)));
    while (it > 0 && it * njt - it * (it - 1) / 2 > bidx) it--;
    while ((it + 1) * njt - (it + 1) * it / 2 <= bidx) it++;
    const int jt = it + (bidx - (it * njt - it * (it - 1) / 2));

    extern __shared__ __align__(128) char smc[];
    const uint32_t sb = smem_u32(smc);

    const int tid    = threadIdx.x;
    const int wid    = tid >> 5;
    const int lane   = tid & 31;
    const int warp_m = wid & 3;   // rows warp_m*32
    const int warp_n = wid >> 2;  // cols warp_n*64
    const int i0     = it * 128;
    const int j0     = jt * 128;
    const bool diag  = (it == jt);

    // stage per-row/col metadata; zero transpose accumulators
    {
        int t = tid & 127;
        if (tid < 128) {
            int gi = i0 + t;
            ((int*)(smc + OFF_SS))[t]     = starts[gi];
            ((int*)(smc + OFF_SE))[t]     = ends[gi];
            ((float*)(smc + OFF_SQI))[t]  = g_sq[gi];
            ((float*)(smc + OFF_INVI))[t] = g_invn[gi];
            ((float*)(smc + OFF_CTP))[t]  = 0.f;
        } else {
            int gj = j0 + t;
            ((float*)(smc + OFF_SQJ))[t]  = g_sq[gj];
            ((float*)(smc + OFF_INVJ))[t] = g_invn[gj];
            ((int*)(smc + OFF_SS2))[t]    = starts[gj];
            ((int*)(smc + OFF_SE2))[t]    = ends[gj];
            ((float*)(smc + OFF_CTN))[t]  = 0.f;
        }
    }

    float acc[2][8][4];
    #pragma unroll
    for (int m = 0; m < 2; m++)
        #pragma unroll
        for (int g = 0; g < 8; g++)
            #pragma unroll
            for (int e = 0; e < 4; e++) acc[m][g][e] = 0.f;

    const unsigned char* __restrict__ cb8 = g_cb8;

    // BK=64 fp8 elements = 64 bytes/row. 128 rows x 4 x 16B = 512 segs/tile.
    auto load_chunk = [&](int c, int b) {
        const int k0 = c * 64;
        const uint32_t ab = sb + (uint32_t)b * BUF_BYTES;
        const uint32_t bbse = ab + TILE_BYTES;
        #pragma unroll
        for (int t = 0; t < 2; t++) {
            int seg = tid + t * 256;
            int r = seg >> 2, qc = seg & 3;
            cp16(ab + tile_off(r, qc * 16),
                 cb8 + (size_t)(i0 + r) * d + k0 + qc * 16);
        }
        #pragma unroll
        for (int t = 0; t < 2; t++) {
            int seg = tid + t * 256;
            int r = seg >> 2, qc = seg & 3;
            cp16(bbse + tile_off(r, qc * 16),
                 cb8 + (size_t)(j0 + r) * d + k0 + qc * 16);
        }
        CP_COMMIT();
    };

    const int NC = d >> 6;   // chunks of BK=64
    load_chunk(0, 0);
    if (NC > 1) load_chunk(1, 1);
    if (NC > 2) load_chunk(2, 2);
    if (NC > 3) load_chunk(3, 3);

    for (int c = 0; c < NC; c++) {
        // ensure chunk c complete (pending = #chunks issued beyond c)
        if (c + 3 < NC)      asm volatile("cp.async.wait_group 3;" ::: "memory");
        else if (c + 2 < NC) asm volatile("cp.async.wait_group 2;" ::: "memory");
        else if (c + 1 < NC) asm volatile("cp.async.wait_group 1;" ::: "memory");
        else                 asm volatile("cp.async.wait_group 0;" ::: "memory");
        // single barrier: stage-c data visible; all warps done with stage c-1,
        // so buffer (c+4)%5 == (c-1)%5 is free for refill.
        __syncthreads();
        if (c + 4 < NC) load_chunk(c + 4, (c + 4) % NSTAGE);

        const uint32_t Ab = sb + (uint32_t)(c % NSTAGE) * BUF_BYTES;
        const uint32_t Bb = Ab + TILE_BYTES;

        #pragma unroll
        for (int ks = 0; ks < 2; ks++) {
            const int kb = ks * 32;   // byte offset of this K=32(e4m3) slice
            uint32_t a[2][4];
            #pragma unroll
            for (int m = 0; m < 2; m++) {
                int row = warp_m * 32 + m * 16 + (lane & 15);
                uint32_t addr = Ab + tile_off(row, kb + (lane >> 4) * 16);
                ldm_x4(a[m][0], a[m][1], a[m][2], a[m][3], addr);
            }
            uint32_t bf[4][4];
            #pragma unroll
            for (int g = 0; g < 4; g++) {
                int sel = lane >> 3;
                int row = warp_n * 64 + g * 16 + (sel & 1) * 8 + (lane & 7);
                uint32_t addr = Bb + tile_off(row, kb + (sel >> 1) * 16);
                ldm_x4(bf[g][0], bf[g][1], bf[g][2], bf[g][3], addr);
            }
            #pragma unroll
            for (int m = 0; m < 2; m++)
                #pragma unroll
                for (int g = 0; g < 4; g++) {
                    mma_fp8(acc[m][2 * g],     a[m][0], a[m][1], a[m][2], a[m][3],
                            bf[g][0], bf[g][2]);
                    mma_fp8(acc[m][2 * g + 1], a[m][0], a[m][1], a[m][2], a[m][3],
                            bf[g][1], bf[g][3]);
                }
        }
    }

    // --- epilogue (normal orientation: rows = i-block, partial slot jt) ---
    const int M = min(N, pmaxi[0] + 1);
    const int rq = lane >> 2;
    const int cq = lane & 3;

    const int*   sS    = (const int*)(smc + OFF_SS);
    const int*   sE    = (const int*)(smc + OFF_SE);
    const float* sqi_  = (const float*)(smc + OFF_SQI);
    const float* invi_ = (const float*)(smc + OFF_INVI);
    const float* sqj_  = (const float*)(smc + OFF_SQJ);
    const float* invj_ = (const float*)(smc + OFF_INVJ);
    const int*   sS2   = (const int*)(smc + OFF_SS2);
    const int*   sE2   = (const int*)(smc + OFF_SE2);
    float* combP = (float*)(smc + OFF_COMBP);
    float* combN = (float*)(smc + OFF_COMBN);
    float* ctP   = (float*)(smc + OFF_CTP);
    float* ctN   = (float*)(smc + OFF_CTN);

    float posL[2][2], negL[2][2];
    #pragma unroll
    for (int m = 0; m < 2; m++) {
        #pragma unroll
        for (int h = 0; h < 2; h++) {
            int rl = warp_m * 32 + m * 16 + h * 8 + rq;
            int gi = i0 + rl;
            float pos = 0.f, neg = 0.f;
            if (gi < M) {
                int   s_  = sS[rl],   e_   = sE[rl];
                float sqi = sqi_[rl], invi = invi_[rl];
                #pragma unroll
                for (int g = 0; g < 8; g++) {
                    #pragma unroll
                    for (int ee = 0; ee < 2; ee++) {
                        int cl = warp_n * 64 + g * 8 + cq * 2 + ee;
                        int gj = j0 + cl;
                        float dot = acc[m][g][h * 2 + ee];
                        bool pm = (gj >= s_) && (gj <= e_) && (gj != gi);
                        if (pm) {
                            float d2 = fmaxf(sqi + sqj_[cl] - 2.f * dot, 0.f);
                            float t  = sqrtf(d2) - M_POS;
                            if (t > 0.f) pos = fmaf(t, t, pos);
                        } else {
                            float cs = fminf(1.f, fmaxf(-1.f, dot * invi * invj_[cl]));
                            float a  = fabsf(cs) - M_NEG_SIM;
                            if (a > 0.f) neg = fmaf(a, a, neg);
                        }
                    }
                }
            }
            pos += __shfl_xor_sync(0xffffffffu, pos, 1);
            pos += __shfl_xor_sync(0xffffffffu, pos, 2);
            neg += __shfl_xor_sync(0xffffffffu, neg, 1);
            neg += __shfl_xor_sync(0xffffffffu, neg, 2);
            if (cq == 0 && warp_n == 1) { combP[rl] = pos; combN[rl] = neg; }
            posL[m][h] = pos;  negL[m][h] = neg;
        }
    }
    __syncthreads();
    if (warp_n == 0 && cq == 0) {
        #pragma unroll
        for (int m = 0; m < 2; m++)
            #pragma unroll
            for (int h = 0; h < 2; h++) {
                int rl = warp_m * 32 + m * 16 + h * 8 + rq;
                int gi = i0 + rl;
                g_pos_part[jt * N + gi] = posL[m][h] + combP[rl];
                g_neg_part[jt * N + gi] = negL[m][h] + combN[rl];
            }
    }

    // --- transposed epilogue (off-diagonal only): rows = j-block, slot it ---
    if (!diag) {
        float pcol[16], ncol[16];
        #pragma unroll
        for (int q = 0; q < 16; q++) { pcol[q] = 0.f; ncol[q] = 0.f; }

        #pragma unroll
        for (int m = 0; m < 2; m++) {
            #pragma unroll
            for (int h = 0; h < 2; h++) {
                int rl = warp_m * 32 + m * 16 + h * 8 + rq;
                float sqc  = sqi_[rl];    // i-row acts as column
                float invc = invi_[rl];
                int gic = i0 + rl;
                #pragma unroll
                for (int g = 0; g < 8; g++) {
                    #pragma unroll
                    for (int ee = 0; ee < 2; ee++) {
                        int cl = warp_n * 64 + g * 8 + cq * 2 + ee;
                        int gjr = j0 + cl;          // j acts as row
                        float dot = acc[m][g][h * 2 + ee];
                        if (gjr < M) {
                            int s_ = sS2[cl], e_ = sE2[cl];
                            int q_ = g * 2 + ee;
                            bool pm = (gic >= s_) && (gic <= e_);
                            if (pm) {
                                float d2 = fmaxf(sqj_[cl] + sqc - 2.f * dot, 0.f);
                                float t  = sqrtf(d2) - M_POS;
                                if (t > 0.f) pcol[q_] = fmaf(t, t, pcol[q_]);
                            } else {
                                float cs = fminf(1.f, fmaxf(-1.f, dot * invj_[cl] * invc));
                                float a  = fabsf(cs) - M_NEG_SIM;
                                if (a > 0.f) ncol[q_] = fmaf(a, a, ncol[q_]);
                            }
                        }
                    }
                }
            }
        }
        #pragma unroll
        for (int q = 0; q < 16; q++) {
            #pragma unroll
            for (int off = 4; off <= 16; off <<= 1) {
                pcol[q] += __shfl_xor_sync(0xffffffffu, pcol[q], off);
                ncol[q] += __shfl_xor_sync(0xffffffffu, ncol[q], off);
            }
        }
        if (rq == 0) {
            #pragma unroll
            for (int g = 0; g < 8; g++) {
                #pragma unroll
                for (int ee = 0; ee < 2; ee++) {
                    int cl = warp_n * 64 + g * 8 + cq * 2 + ee;
                    atomicAdd(&ctP[cl], pcol[g * 2 + ee]);
                    atomicAdd(&ctN[cl], ncol[g * 2 + ee]);
                }
            }
        }
        __syncthreads();
        if (tid < 128) {
            int gj = j0 + tid;
            g_pos_part[it * N + gj] = ctP[tid];
            g_neg_part[it * N + gj] = ctN[tid];
        }
    }
}

// ---------------------------------------------------------------------------
// Pass 3: per-row combine + block reduction + global atomic accumulate
// ---------------------------------------------------------------------------
__global__ void k_rowsum(const int* __restrict__ starts,
                         const int* __restrict__ ends,
                         const int* __restrict__ pmaxi,
                         int N, int njt) {
    int i = blockIdx.x * blockDim.x + threadIdx.x;
    float pr = 0.f;
    int vl = 0;
    if (i < N) {
        int M = min(N, pmaxi[0] + 1);
        float ps = 0.f, ns = 0.f;
        int t = 0;
        for (; t + 8 <= njt; t += 8) {
            float p0 = g_pos_part[(t + 0) * N + i], n0 = g_neg_part[(t + 0) * N + i];
            float p1 = g_pos_part[(t + 1) * N + i], n1 = g_neg_part[(t + 1) * N + i];
            float p2 = g_pos_part[(t + 2) * N + i], n2 = g_neg_part[(t + 2) * N + i];
            float p3 = g_pos_part[(t + 3) * N + i], n3 = g_neg_part[(t + 3) * N + i];
            float p4 = g_pos_part[(t + 4) * N + i], n4 = g_neg_part[(t + 4) * N + i];
            float p5 = g_pos_part[(t + 5) * N + i], n5 = g_neg_part[(t + 5) * N + i];
            float p6 = g_pos_part[(t + 6) * N + i], n6 = g_neg_part[(t + 6) * N + i];
            float p7 = g_pos_part[(t + 7) * N + i], n7 = g_neg_part[(t + 7) * N + i];
            ps += ((p0 + p1) + (p2 + p3)) + ((p4 + p5) + (p6 + p7));
            ns += ((n0 + n1) + (n2 + n3)) + ((n4 + n5) + (n6 + n7));
        }
        for (; t < njt; t++) {
            ps += g_pos_part[t * N + i];
            ns += g_neg_part[t * N + i];
        }
        int s = starts[i], e = ends[i];
        int lo = s < 0 ? 0 : s;
        int hi = e > N - 1 ? N - 1 : e;
        int cin = hi - lo + 1; if (cin < 0) cin = 0;
        int iin = (i >= s && i <= e) ? 1 : 0;
        int pc = cin - iin;
        int nc = N - cin + iin;
        bool valid = (i < M) && (pc > 0) && (nc > 0);
        if (valid) {
            pr = ps / (float)(pc < 1 ? 1 : pc) + LAM_NEG * ns / (float)(nc < 1 ? 1 : nc);
            vl = 1;
        }
    }
    // block reduction
    #pragma unroll
    for (int off = 16; off; off >>= 1) {
        pr += __shfl_down_sync(0xffffffffu, pr, off);
        vl += __shfl_down_sync(0xffffffffu, vl, off);
    }
    __shared__ float sh[8];
    __shared__ int   shc[8];
    if ((threadIdx.x & 31) == 0) { sh[threadIdx.x >> 5] = pr; shc[threadIdx.x >> 5] = vl; }
    __syncthreads();
    if (threadIdx.x < 8) {
        pr = sh[threadIdx.x];  vl = shc[threadIdx.x];
        #pragma unroll
        for (int off = 4; off; off >>= 1) {
            pr += __shfl_down_sync(0xffu, pr, off);
            vl += __shfl_down_sync(0xffu, vl, off);
        }
        if (threadIdx.x == 0) {
            atomicAdd(&g_tot, pr);
            atomicAdd(&g_cnt, vl);
        }
    }
}

// ---------------------------------------------------------------------------
// Pass 4: trivial final division
// ---------------------------------------------------------------------------
__global__ void k_write(float* __restrict__ out) {
    if (threadIdx.x == 0)
        out[0] = (g_cnt > 0) ? g_tot / (float)g_cnt : 0.f;
}

// ---------------------------------------------------------------------------
// Launch
// ---------------------------------------------------------------------------
extern "C" void kernel_launch(void* const* d_in, const int* in_sizes, int n_in,
                              void* d_out, int out_size) {
    const float* cb     = (const float*)d_in[0];
    const int*   starts = (const int*)d_in[1];
    const int*   ends   = (const int*)d_in[2];
    const int*   pmaxi  = (const int*)d_in[3];

    int N = in_sizes[1];             // starts has N elements
    int d = in_sizes[0] / N;         // codebook is N x d

    cudaFuncSetAttribute(k_main, cudaFuncAttributeMaxDynamicSharedMemorySize,
                         (int)SMEM_TOTAL);

    k_prep<<<(N + 7) / 8, 256>>>(cb, N, d);

    int njt = N / 128;
    int ntri = njt * (njt + 1) / 2;
    k_main<<<ntri, 256, SMEM_TOTAL>>>(starts, ends, pmaxi, N, d, njt);

    k_rowsum<<<(N + 255) / 256, 256>>>(starts, ends, pmaxi, N, njt);
    k_write<<<1, 32>>>((float*)d_out);
}

// round 15
// speedup vs baseline: 1.0815x; 1.0064x over previous
#include <cuda_runtime.h>
#include <cuda_bf16.h>
#include <cuda_fp8.h>
#include <math.h>
#include <stdint.h>

// Fixed problem envelope (dataset: N=8192, d=1024). Requires N%128==0, d%64==0.
#define MAXN 8192
#define MAXD 1024
#define MAXJT 64   // N/128

#define M_POS 0.5f
#define M_NEG_SIM 0.1f
#define LAM_NEG 1.0f

// ---------------------------------------------------------------------------
// Device scratch (allocation-free rule: __device__ globals)
// ---------------------------------------------------------------------------
__device__ __align__(16) unsigned char g_cb8[MAXN * MAXD];  // e4m3 codebook (8MB)
__device__ float g_sq[MAXN];
__device__ float g_invn[MAXN];
__device__ float g_pos_part[MAXJT * MAXN];
__device__ float g_neg_part[MAXJT * MAXN];
__device__ float g_tot;
__device__ int   g_cnt;

// ---------------------------------------------------------------------------
// PTX helpers
// ---------------------------------------------------------------------------
__device__ __forceinline__ uint32_t smem_u32(const void* p) {
    uint32_t a;
    asm("{ .reg .u64 t; cvta.to.shared.u64 t, %1; cvt.u32.u64 %0, t; }"
        : "=r"(a) : "l"(p));
    return a;
}

__device__ __forceinline__ void cp16(uint32_t dst, const void* src) {
    asm volatile("cp.async.cg.shared.global [%0], [%1], 16;"
                 :: "r"(dst), "l"(src) : "memory");
}
#define CP_COMMIT() asm volatile("cp.async.commit_group;" ::: "memory")

__device__ __forceinline__ void ldm_x4(uint32_t& r0, uint32_t& r1,
                                       uint32_t& r2, uint32_t& r3, uint32_t addr) {
    asm volatile("ldmatrix.sync.aligned.m8n8.x4.shared.b16 {%0,%1,%2,%3}, [%4];"
                 : "=r"(r0), "=r"(r1), "=r"(r2), "=r"(r3) : "r"(addr));
}

// FP8 e4m3 MMA: m16n8k32, fp32 accumulate. Fragment byte layout matches the
// bf16 m16n8k16 pattern (4-byte k-groups per lane), so ldmatrix.b16 loads work.
__device__ __forceinline__ void mma_fp8(float* c, uint32_t a0, uint32_t a1,
                                        uint32_t a2, uint32_t a3,
                                        uint32_t b0, uint32_t b1) {
    asm volatile(
        "mma.sync.aligned.m16n8k32.row.col.f32.e4m3.e4m3.f32 "
        "{%0,%1,%2,%3}, {%4,%5,%6,%7}, {%8,%9}, {%0,%1,%2,%3};"
        : "+f"(c[0]), "+f"(c[1]), "+f"(c[2]), "+f"(c[3])
        : "r"(a0), "r"(a1), "r"(a2), "r"(a3), "r"(b0), "r"(b1));
}

// XOR-swizzled tile layout: 128 logical rows x 64 B (BK=64 fp8) packed as
// 64 physical rows x 128B.  off0 = (r>>1)*128 + (r&1)*64 + kbyte;
// phys = off0 ^ ((off0>>3)&0x70).  Conflict-free for cp.async stores AND
// ldmatrix reads (verified against the 32-bank model).
__device__ __forceinline__ uint32_t tile_off(int r, int kbyte) {
    uint32_t off0 = ((uint32_t)(r >> 1) << 7) + ((uint32_t)(r & 1) << 6)
                  + (uint32_t)kbyte;
    return off0 ^ ((off0 >> 3) & 0x70);
}

// SMEM layout (bytes, relative to dynamic smem base). 5-stage pipeline.
#define TILE_BYTES  8192u             // 64 * 128
#define BUF_BYTES   16384u            // A + B per stage
#define NSTAGE      5
#define OFF_META    81920u            // after 5 stages
#define OFF_SS      (OFF_META + 0u)     // int[128]   starts of i-block
#define OFF_SE      (OFF_META + 512u)   // int[128]   ends of i-block
#define OFF_SQI     (OFF_META + 1024u)  // float[128]
#define OFF_INVI    (OFF_META + 1536u)  // float[128]
#define OFF_SQJ     (OFF_META + 2048u)  // float[128]
#define OFF_INVJ    (OFF_META + 2560u)  // float[128]
#define OFF_COMBP   (OFF_META + 3072u)  // float[128]
#define OFF_COMBN   (OFF_META + 3584u)  // float[128]
#define OFF_SS2     (OFF_META + 4096u)  // int[128]   starts of j-block
#define OFF_SE2     (OFF_META + 4608u)  // int[128]   ends of j-block
#define OFF_CTP     (OFF_META + 5120u)  // float[128] transpose pos accum
#define OFF_CTN     (OFF_META + 5632u)  // float[128] transpose neg accum
#define SMEM_TOTAL  (OFF_META + 6144u)

// ---------------------------------------------------------------------------
// Pass 0+1 fused: fp32 -> e4m3 conversion + per-row norms, WARP-PER-ROW
// (8 rows per 256-thread block). Also zeroes the global loss accumulators.
// ---------------------------------------------------------------------------
__global__ __launch_bounds__(256) void k_prep(const float* __restrict__ cb,
                                              int N, int d) {
    if (blockIdx.x == 0 && threadIdx.x == 0) { g_tot = 0.f; g_cnt = 0; }
    int wid  = threadIdx.x >> 5;
    int lane = threadIdx.x & 31;
    int row  = blockIdx.x * 8 + wid;
    if (row >= N) return;
    const float* p = cb + (size_t)row * d;
    unsigned char* o = g_cb8 + (size_t)row * d;
    float s = 0.f;
    for (int c = lane * 8; c < d; c += 32 * 8) {
        float4 v0 = *(const float4*)(p + c);
        float4 v1 = *(const float4*)(p + c + 4);
        s = fmaf(v0.x, v0.x, s);  s = fmaf(v0.y, v0.y, s);
        s = fmaf(v0.z, v0.z, s);  s = fmaf(v0.w, v0.w, s);
        s = fmaf(v1.x, v1.x, s);  s = fmaf(v1.y, v1.y, s);
        s = fmaf(v1.z, v1.z, s);  s = fmaf(v1.w, v1.w, s);
        uint32_t q0 = (uint32_t)__nv_cvt_float2_to_fp8x2(
                          make_float2(v0.x, v0.y), __NV_SATFINITE, __NV_E4M3);
        uint32_t q1 = (uint32_t)__nv_cvt_float2_to_fp8x2(
                          make_float2(v0.z, v0.w), __NV_SATFINITE, __NV_E4M3);
        uint32_t q2 = (uint32_t)__nv_cvt_float2_to_fp8x2(
                          make_float2(v1.x, v1.y), __NV_SATFINITE, __NV_E4M3);
        uint32_t q3 = (uint32_t)__nv_cvt_float2_to_fp8x2(
                          make_float2(v1.z, v1.w), __NV_SATFINITE, __NV_E4M3);
        uint2 w;
        w.x = q0 | (q1 << 16);
        w.y = q2 | (q3 << 16);
        *(uint2*)(o + c) = w;
    }
    #pragma unroll
    for (int off = 16; off; off >>= 1) s += __shfl_down_sync(0xffffffffu, s, off);
    if (lane == 0) {
        g_sq[row]   = s;
        g_invn[row] = rsqrtf(fmaxf(s, 1e-30f));
    }
}

// ---------------------------------------------------------------------------
// Pass 2: FP8 MMA Gram tile 128x128, SYMMETRIC, 1D triangular grid,
// 5-stage cp.async pipeline, XOR-swizzled conflict-free SMEM, 2 CTAs/SM.
// (Byte-identical mainloop/epilogue to the 256.5us best configuration.)
// ---------------------------------------------------------------------------
__global__ __launch_bounds__(256, 2) void k_main(
    const int* __restrict__ starts,
    const int* __restrict__ ends,
    const int* __restrict__ pmaxi,
    int N, int d, int njt)
{
    // map linear block id -> upper-triangular (it, jt), it <= jt
    int bidx = blockIdx.x;
    float nf = (float)njt + 0.5f;
    int it = (int)(nf - sqrtf(fmaxf(nf * nf - 2.0f * (float)bidx, 0.f)));
    while (it > 0 && it * njt - it * (it - 1) / 2 > bidx) it--;
    while ((it + 1) * njt - (it + 1) * it / 2 <= bidx) it++;
    const int jt = it + (bidx - (it * njt - it * (it - 1) / 2));

    extern __shared__ __align__(128) char smc[];
    const uint32_t sb = smem_u32(smc);

    const int tid    = threadIdx.x;
    const int wid    = tid >> 5;
    const int lane   = tid & 31;
    const int warp_m = wid & 3;   // rows warp_m*32
    const int warp_n = wid >> 2;  // cols warp_n*64
    const int i0     = it * 128;
    const int j0     = jt * 128;
    const bool diag  = (it == jt);

    // stage per-row/col metadata; zero transpose accumulators
    {
        int t = tid & 127;
        if (tid < 128) {
            int gi = i0 + t;
            ((int*)(smc + OFF_SS))[t]     = starts[gi];
            ((int*)(smc + OFF_SE))[t]     = ends[gi];
            ((float*)(smc + OFF_SQI))[t]  = g_sq[gi];
            ((float*)(smc + OFF_INVI))[t] = g_invn[gi];
            ((float*)(smc + OFF_CTP))[t]  = 0.f;
        } else {
            int gj = j0 + t;
            ((float*)(smc + OFF_SQJ))[t]  = g_sq[gj];
            ((float*)(smc + OFF_INVJ))[t] = g_invn[gj];
            ((int*)(smc + OFF_SS2))[t]    = starts[gj];
            ((int*)(smc + OFF_SE2))[t]    = ends[gj];
            ((float*)(smc + OFF_CTN))[t]  = 0.f;
        }
    }

    float acc[2][8][4];
    #pragma unroll
    for (int m = 0; m < 2; m++)
        #pragma unroll
        for (int g = 0; g < 8; g++)
            #pragma unroll
            for (int e = 0; e < 4; e++) acc[m][g][e] = 0.f;

    const unsigned char* __restrict__ cb8 = g_cb8;

    // BK=64 fp8 elements = 64 bytes/row. 128 rows x 4 x 16B = 512 segs/tile.
    auto load_chunk = [&](int c, int b) {
        const int k0 = c * 64;
        const uint32_t ab = sb + (uint32_t)b * BUF_BYTES;
        const uint32_t bbse = ab + TILE_BYTES;
        #pragma unroll
        for (int t = 0; t < 2; t++) {
            int seg = tid + t * 256;
            int r = seg >> 2, qc = seg & 3;
            cp16(ab + tile_off(r, qc * 16),
                 cb8 + (size_t)(i0 + r) * d + k0 + qc * 16);
        }
        #pragma unroll
        for (int t = 0; t < 2; t++) {
            int seg = tid + t * 256;
            int r = seg >> 2, qc = seg & 3;
            cp16(bbse + tile_off(r, qc * 16),
                 cb8 + (size_t)(j0 + r) * d + k0 + qc * 16);
        }
        CP_COMMIT();
    };

    const int NC = d >> 6;   // chunks of BK=64
    load_chunk(0, 0);
    if (NC > 1) load_chunk(1, 1);
    if (NC > 2) load_chunk(2, 2);
    if (NC > 3) load_chunk(3, 3);

    for (int c = 0; c < NC; c++) {
        // ensure chunk c complete (pending = #chunks issued beyond c)
        if (c + 3 < NC)      asm volatile("cp.async.wait_group 3;" ::: "memory");
        else if (c + 2 < NC) asm volatile("cp.async.wait_group 2;" ::: "memory");
        else if (c + 1 < NC) asm volatile("cp.async.wait_group 1;" ::: "memory");
        else                 asm volatile("cp.async.wait_group 0;" ::: "memory");
        // single barrier: stage-c data visible; all warps done with stage c-1,
        // so buffer (c+4)%5 == (c-1)%5 is free for refill.
        __syncthreads();
        if (c + 4 < NC) load_chunk(c + 4, (c + 4) % NSTAGE);

        const uint32_t Ab = sb + (uint32_t)(c % NSTAGE) * BUF_BYTES;
        const uint32_t Bb = Ab + TILE_BYTES;

        #pragma unroll
        for (int ks = 0; ks < 2; ks++) {
            const int kb = ks * 32;   // byte offset of this K=32(e4m3) slice
            uint32_t a[2][4];
            #pragma unroll
            for (int m = 0; m < 2; m++) {
                int row = warp_m * 32 + m * 16 + (lane & 15);
                uint32_t addr = Ab + tile_off(row, kb + (lane >> 4) * 16);
                ldm_x4(a[m][0], a[m][1], a[m][2], a[m][3], addr);
            }
            uint32_t bf[4][4];
            #pragma unroll
            for (int g = 0; g < 4; g++) {
                int sel = lane >> 3;
                int row = warp_n * 64 + g * 16 + (sel & 1) * 8 + (lane & 7);
                uint32_t addr = Bb + tile_off(row, kb + (sel >> 1) * 16);
                ldm_x4(bf[g][0], bf[g][1], bf[g][2], bf[g][3], addr);
            }
            #pragma unroll
            for (int m = 0; m < 2; m++)
                #pragma unroll
                for (int g = 0; g < 4; g++) {
                    mma_fp8(acc[m][2 * g],     a[m][0], a[m][1], a[m][2], a[m][3],
                            bf[g][0], bf[g][2]);
                    mma_fp8(acc[m][2 * g + 1], a[m][0], a[m][1], a[m][2], a[m][3],
                            bf[g][1], bf[g][3]);
                }
        }
    }

    // --- epilogue (normal orientation: rows = i-block, partial slot jt) ---
    const int M = min(N, pmaxi[0] + 1);
    const int rq = lane >> 2;
    const int cq = lane & 3;

    const int*   sS    = (const int*)(smc + OFF_SS);
    const int*   sE    = (const int*)(smc + OFF_SE);
    const float* sqi_  = (const float*)(smc + OFF_SQI);
    const float* invi_ = (const float*)(smc + OFF_INVI);
    const float* sqj_  = (const float*)(smc + OFF_SQJ);
    const float* invj_ = (const float*)(smc + OFF_INVJ);
    const int*   sS2   = (const int*)(smc + OFF_SS2);
    const int*   sE2   = (const int*)(smc + OFF_SE2);
    float* combP = (float*)(smc + OFF_COMBP);
    float* combN = (float*)(smc + OFF_COMBN);
    float* ctP   = (float*)(smc + OFF_CTP);
    float* ctN   = (float*)(smc + OFF_CTN);

    float posL[2][2], negL[2][2];
    #pragma unroll
    for (int m = 0; m < 2; m++) {
        #pragma unroll
        for (int h = 0; h < 2; h++) {
            int rl = warp_m * 32 + m * 16 + h * 8 + rq;
            int gi = i0 + rl;
            float pos = 0.f, neg = 0.f;
            if (gi < M) {
                int   s_  = sS[rl],   e_   = sE[rl];
                float sqi = sqi_[rl], invi = invi_[rl];
                #pragma unroll
                for (int g = 0; g < 8; g++) {
                    #pragma unroll
                    for (int ee = 0; ee < 2; ee++) {
                        int cl = warp_n * 64 + g * 8 + cq * 2 + ee;
                        int gj = j0 + cl;
                        float dot = acc[m][g][h * 2 + ee];
                        bool pm = (gj >= s_) && (gj <= e_) && (gj != gi);
                        if (pm) {
                            float d2 = fmaxf(sqi + sqj_[cl] - 2.f * dot, 0.f);
                            float t  = sqrtf(d2) - M_POS;
                            if (t > 0.f) pos = fmaf(t, t, pos);
                        } else {
                            float cs = fminf(1.f, fmaxf(-1.f, dot * invi * invj_[cl]));
                            float a  = fabsf(cs) - M_NEG_SIM;
                            if (a > 0.f) neg = fmaf(a, a, neg);
                        }
                    }
                }
            }
            pos += __shfl_xor_sync(0xffffffffu, pos, 1);
            pos += __shfl_xor_sync(0xffffffffu, pos, 2);
            neg += __shfl_xor_sync(0xffffffffu, neg, 1);
            neg += __shfl_xor_sync(0xffffffffu, neg, 2);
            if (cq == 0 && warp_n == 1) { combP[rl] = pos; combN[rl] = neg; }
            posL[m][h] = pos;  negL[m][h] = neg;
        }
    }
    __syncthreads();
    if (warp_n == 0 && cq == 0) {
        #pragma unroll
        for (int m = 0; m < 2; m++)
            #pragma unroll
            for (int h = 0; h < 2; h++) {
                int rl = warp_m * 32 + m * 16 + h * 8 + rq;
                int gi = i0 + rl;
                g_pos_part[jt * N + gi] = posL[m][h] + combP[rl];
                g_neg_part[jt * N + gi] = negL[m][h] + combN[rl];
            }
    }

    // --- transposed epilogue (off-diagonal only): rows = j-block, slot it ---
    if (!diag) {
        float pcol[16], ncol[16];
        #pragma unroll
        for (int q = 0; q < 16; q++) { pcol[q] = 0.f; ncol[q] = 0.f; }

        #pragma unroll
        for (int m = 0; m < 2; m++) {
            #pragma unroll
            for (int h = 0; h < 2; h++) {
                int rl = warp_m * 32 + m * 16 + h * 8 + rq;
                float sqc  = sqi_[rl];    // i-row acts as column
                float invc = invi_[rl];
                int gic = i0 + rl;
                #pragma unroll
                for (int g = 0; g < 8; g++) {
                    #pragma unroll
                    for (int ee = 0; ee < 2; ee++) {
                        int cl = warp_n * 64 + g * 8 + cq * 2 + ee;
                        int gjr = j0 + cl;          // j acts as row
                        float dot = acc[m][g][h * 2 + ee];
                        if (gjr < M) {
                            int s_ = sS2[cl], e_ = sE2[cl];
                            int q_ = g * 2 + ee;
                            bool pm = (gic >= s_) && (gic <= e_);
                            if (pm) {
                                float d2 = fmaxf(sqj_[cl] + sqc - 2.f * dot, 0.f);
                                float t  = sqrtf(d2) - M_POS;
                                if (t > 0.f) pcol[q_] = fmaf(t, t, pcol[q_]);
                            } else {
                                float cs = fminf(1.f, fmaxf(-1.f, dot * invj_[cl] * invc));
                                float a  = fabsf(cs) - M_NEG_SIM;
                                if (a > 0.f) ncol[q_] = fmaf(a, a, ncol[q_]);
                            }
                        }
                    }
                }
            }
        }
        #pragma unroll
        for (int q = 0; q < 16; q++) {
            #pragma unroll
            for (int off = 4; off <= 16; off <<= 1) {
                pcol[q] += __shfl_xor_sync(0xffffffffu, pcol[q], off);
                ncol[q] += __shfl_xor_sync(0xffffffffu, ncol[q], off);
            }
        }
        if (rq == 0) {
            #pragma unroll
            for (int g = 0; g < 8; g++) {
                #pragma unroll
                for (int ee = 0; ee < 2; ee++) {
                    int cl = warp_n * 64 + g * 8 + cq * 2 + ee;
                    atomicAdd(&ctP[cl], pcol[g * 2 + ee]);
                    atomicAdd(&ctN[cl], ncol[g * 2 + ee]);
                }
            }
        }
        __syncthreads();
        if (tid < 128) {
            int gj = j0 + tid;
            g_pos_part[it * N + gj] = ctP[tid];
            g_neg_part[it * N + gj] = ctN[tid];
        }
    }
}

// ---------------------------------------------------------------------------
// Pass 3: per-row combine + block reduction + global atomic accumulate
// ---------------------------------------------------------------------------
__global__ void k_rowsum(const int* __restrict__ starts,
                         const int* __restrict__ ends,
                         const int* __restrict__ pmaxi,
                         int N, int njt) {
    int i = blockIdx.x * blockDim.x + threadIdx.x;
    float pr = 0.f;
    int vl = 0;
    if (i < N) {
        int M = min(N, pmaxi[0] + 1);
        float ps = 0.f, ns = 0.f;
        int t = 0;
        for (; t + 8 <= njt; t += 8) {
            float p0 = g_pos_part[(t + 0) * N + i], n0 = g_neg_part[(t + 0) * N + i];
            float p1 = g_pos_part[(t + 1) * N + i], n1 = g_neg_part[(t + 1) * N + i];
            float p2 = g_pos_part[(t + 2) * N + i], n2 = g_neg_part[(t + 2) * N + i];
            float p3 = g_pos_part[(t + 3) * N + i], n3 = g_neg_part[(t + 3) * N + i];
            float p4 = g_pos_part[(t + 4) * N + i], n4 = g_neg_part[(t + 4) * N + i];
            float p5 = g_pos_part[(t + 5) * N + i], n5 = g_neg_part[(t + 5) * N + i];
            float p6 = g_pos_part[(t + 6) * N + i], n6 = g_neg_part[(t + 6) * N + i];
            float p7 = g_pos_part[(t + 7) * N + i], n7 = g_neg_part[(t + 7) * N + i];
            ps += ((p0 + p1) + (p2 + p3)) + ((p4 + p5) + (p6 + p7));
            ns += ((n0 + n1) + (n2 + n3)) + ((n4 + n5) + (n6 + n7));
        }
        for (; t < njt; t++) {
            ps += g_pos_part[t * N + i];
            ns += g_neg_part[t * N + i];
        }
        int s = starts[i], e = ends[i];
        int lo = s < 0 ? 0 : s;
        int hi = e > N - 1 ? N - 1 : e;
        int cin = hi - lo + 1; if (cin < 0) cin = 0;
        int iin = (i >= s && i <= e) ? 1 : 0;
        int pc = cin - iin;
        int nc = N - cin + iin;
        bool valid = (i < M) && (pc > 0) && (nc > 0);
        if (valid) {
            pr = ps / (float)(pc < 1 ? 1 : pc) + LAM_NEG * ns / (float)(nc < 1 ? 1 : nc);
            vl = 1;
        }
    }
    // block reduction
    #pragma unroll
    for (int off = 16; off; off >>= 1) {
        pr += __shfl_down_sync(0xffffffffu, pr, off);
        vl += __shfl_down_sync(0xffffffffu, vl, off);
    }
    __shared__ float sh[8];
    __shared__ int   shc[8];
    if ((threadIdx.x & 31) == 0) { sh[threadIdx.x >> 5] = pr; shc[threadIdx.x >> 5] = vl; }
    __syncthreads();
    if (threadIdx.x < 8) {
        pr = sh[threadIdx.x];  vl = shc[threadIdx.x];
        #pragma unroll
        for (int off = 4; off; off >>= 1) {
            pr += __shfl_down_sync(0xffu, pr, off);
            vl += __shfl_down_sync(0xffu, vl, off);
        }
        if (threadIdx.x == 0) {
            atomicAdd(&g_tot, pr);
            atomicAdd(&g_cnt, vl);
        }
    }
}

// ---------------------------------------------------------------------------
// Pass 4: trivial final division
// ---------------------------------------------------------------------------
__global__ void k_write(float* __restrict__ out) {
    if (threadIdx.x == 0)
        out[0] = (g_cnt > 0) ? g_tot / (float)g_cnt : 0.f;
}

// ---------------------------------------------------------------------------
// Launch
// ---------------------------------------------------------------------------
extern "C" void kernel_launch(void* const* d_in, const int* in_sizes, int n_in,
                              void* d_out, int out_size) {
    const float* cb     = (const float*)d_in[0];
    const int*   starts = (const int*)d_in[1];
    const int*   ends   = (const int*)d_in[2];
    const int*   pmaxi  = (const int*)d_in[3];

    int N = in_sizes[1];             // starts has N elements
    int d = in_sizes[0] / N;         // codebook is N x d

    cudaFuncSetAttribute(k_main, cudaFuncAttributeMaxDynamicSharedMemorySize,
                         (int)SMEM_TOTAL);

    k_prep<<<(N + 7) / 8, 256>>>(cb, N, d);

    int njt = N / 128;
    int ntri = njt * (njt + 1) / 2;
    k_main<<<ntri, 256, SMEM_TOTAL>>>(starts, ends, pmaxi, N, d, njt);

    k_rowsum<<<(N + 255) / 256, 256>>>(starts, ends, pmaxi, N, njt);
    k_write<<<1, 32>>>((float*)d_out);
}